// round 2
// baseline (speedup 1.0000x reference)
#include <cuda_runtime.h>
#include <cstddef>

// Problem shape (fixed)
#define BB 2
#define HH 12
#define SS 2048
#define DD 64

#define QT 16            // queries per block
#define KT 256           // keys per staged chunk
#define NCHUNK (SS / KT) // 8
#define RS 68            // K/V smem row stride in floats (68*4B=272B, 17x16B odd -> conflict-free LDS.128)
#define PS 2052          // P smem row stride in floats (16B aligned, row bank offset 4)
#define THREADS 256

// smem layout (floats):
//   Qs [QT][RS]        = 1088
//   Ks [KT][RS]        = 17408   (reused for V chunks, then as out-reduction scratch)
//   Ps [QT][PS]        = 32832
//   Ms [KT] (int)      = 256
//   rowsum [QT]        = 16
#define SMEM_FLOATS (QT*RS + KT*RS + QT*PS)
#define SMEM_BYTES  (SMEM_FLOATS*4 + KT*4 + QT*4)

extern __shared__ float smem[];

__global__ __launch_bounds__(THREADS, 1)
void attn_fused_kernel(const float* __restrict__ q,
                       const float* __restrict__ k,
                       const float* __restrict__ v,
                       const int*   __restrict__ mask,
                       float* __restrict__ out,
                       float* __restrict__ probs)
{
    float* Qs = smem;                       // [QT][RS]
    float* Ks = Qs + QT * RS;               // [KT][RS]  (also V chunk / reduction scratch)
    float* Ps = Ks + KT * RS;               // [QT][PS]
    int*   Ms = (int*)(Ps + QT * PS);       // [KT]
    float* rowsum = (float*)(Ms + KT);      // [QT]

    const int tid = threadIdx.x;
    const int bh  = blockIdx.y;             // 0..23  (b*H + h)
    const int b   = bh / HH;
    const int q0  = blockIdx.x * QT;

    const float* qptr  = q + ((size_t)bh * SS + q0) * DD;
    const float* kbase = k + (size_t)bh * SS * DD;
    const float* vbase = v + (size_t)bh * SS * DD;
    const int*   mbase = mask + b * SS;

    // ---- load Q tile (16x64), one float4 per thread ----
    {
        int qi = tid >> 4;
        int dc = (tid & 15) << 2;
        float4 t = *(const float4*)(qptr + qi * DD + dc);
        *(float4*)(Qs + qi * RS + dc) = t;
    }
    if (tid < QT) rowsum[tid] = 0.0f;

    // =======================================================================
    // Phase 1: scores -> exp -> Ps (unnormalized), accumulate rowsums
    // thread (qg = tid/64, kg = tid%64): 4 q rows (4qg..4qg+3),
    // 4 k rows strided (kg, kg+64, kg+128, kg+192) within the 256-key chunk.
    // =======================================================================
    const int qg = tid >> 6;   // 0..3
    const int kg = tid & 63;   // 0..63
    float rsum[4] = {0.f, 0.f, 0.f, 0.f};

    for (int c = 0; c < NCHUNK; ++c) {
        __syncthreads();
        // stage K chunk [KT][DD] into Ks (padded rows), 16 float4 per thread
        {
            const float* kc = kbase + (size_t)c * KT * DD;
            #pragma unroll
            for (int r = 0; r < (KT * DD) / (4 * THREADS); ++r) { // 16
                int lin = r * THREADS + tid;
                int kl  = lin >> 4;            // /16 float4-per-row
                int dc  = (lin & 15) << 2;
                float4 t = *(const float4*)(kc + kl * DD + dc);
                *(float4*)(Ks + kl * RS + dc) = t;
            }
            Ms[tid] = mbase[c * KT + tid];     // KT == THREADS
        }
        __syncthreads();

        float acc[4][4];
        #pragma unroll
        for (int i = 0; i < 4; ++i)
            #pragma unroll
            for (int j = 0; j < 4; ++j) acc[i][j] = 0.0f;

        const float* Qrow = Qs + (4 * qg) * RS;
        #pragma unroll 4
        for (int dc = 0; dc < DD; dc += 4) {
            float4 qv[4], kv[4];
            #pragma unroll
            for (int i = 0; i < 4; ++i) qv[i] = *(const float4*)(Qrow + i * RS + dc);
            #pragma unroll
            for (int j = 0; j < 4; ++j) kv[j] = *(const float4*)(Ks + (kg + 64 * j) * RS + dc);
            #pragma unroll
            for (int i = 0; i < 4; ++i) {
                #pragma unroll
                for (int j = 0; j < 4; ++j) {
                    acc[i][j] += qv[i].x * kv[j].x;
                    acc[i][j] += qv[i].y * kv[j].y;
                    acc[i][j] += qv[i].z * kv[j].z;
                    acc[i][j] += qv[i].w * kv[j].w;
                }
            }
        }

        // exp + mask + store to Ps + rowsum partials
        #pragma unroll
        for (int j = 0; j < 4; ++j) {
            int kl = kg + 64 * j;
            float m = Ms[kl] ? 1.0f : 0.0f;
            int col = c * KT + kl;
            #pragma unroll
            for (int i = 0; i < 4; ++i) {
                float p = m * __expf(acc[i][j] * 0.125f); // 1/sqrt(64)
                Ps[(4 * qg + i) * PS + col] = p;
                rsum[i] += p;
            }
        }
    }
    #pragma unroll
    for (int i = 0; i < 4; ++i) atomicAdd(&rowsum[4 * qg + i], rsum[i]);

    // =======================================================================
    // Phase 2: out = P @ V (unnormalized), V staged per chunk into Ks buffer.
    // thread (ks = tid/64, qg2 = (tid%64)/16, dg = tid%16):
    // 4 q rows x 4 d cols, over its quarter (64 keys) of each chunk.
    // =======================================================================
    const int ksq  = tid >> 6;        // 0..3 key-quarter
    const int rem  = tid & 63;
    const int qg2  = rem >> 4;        // 0..3
    const int dg   = rem & 15;        // 0..15

    float4 oacc[4];
    #pragma unroll
    for (int i = 0; i < 4; ++i) oacc[i] = make_float4(0.f, 0.f, 0.f, 0.f);

    for (int c = 0; c < NCHUNK; ++c) {
        __syncthreads();
        {
            const float* vc = vbase + (size_t)c * KT * DD;
            #pragma unroll
            for (int r = 0; r < (KT * DD) / (4 * THREADS); ++r) {
                int lin = r * THREADS + tid;
                int kl  = lin >> 4;
                int dc  = (lin & 15) << 2;
                float4 t = *(const float4*)(vc + kl * DD + dc);
                *(float4*)(Ks + kl * RS + dc) = t;
            }
        }
        __syncthreads();

        const int colbase = c * KT + ksq * 64;
        #pragma unroll 4
        for (int kk = 0; kk < 64; ++kk) {
            int kl = ksq * 64 + kk;
            float4 v4 = *(const float4*)(Ks + kl * RS + 4 * dg);
            int col = colbase + kk;
            #pragma unroll
            for (int i = 0; i < 4; ++i) {
                float p = Ps[(4 * qg2 + i) * PS + col];
                oacc[i].x += p * v4.x;
                oacc[i].y += p * v4.y;
                oacc[i].z += p * v4.z;
                oacc[i].w += p * v4.w;
            }
        }
    }

    // reduce the 4 key-quarter partials via smem scratch (reuse Ks: 4*16*64 floats)
    __syncthreads();
    float* red = Ks;
    #pragma unroll
    for (int i = 0; i < 4; ++i)
        *(float4*)(red + ((ksq * QT + 4 * qg2 + i) * DD) + 4 * dg) = oacc[i];
    __syncthreads();

    // ---- epilogue: out = (sum of partials) / rowsum ----
    {
        int qi = tid >> 4;
        int dc = (tid & 15) << 2;
        float4 a = *(const float4*)(red + ((0 * QT + qi) * DD) + dc);
        #pragma unroll
        for (int s = 1; s < 4; ++s) {
            float4 t = *(const float4*)(red + ((s * QT + qi) * DD) + dc);
            a.x += t.x; a.y += t.y; a.z += t.z; a.w += t.w;
        }
        float rinv = 1.0f / rowsum[qi];
        a.x *= rinv; a.y *= rinv; a.z *= rinv; a.w *= rinv;
        *(float4*)(out + ((size_t)bh * SS + q0 + qi) * DD + dc) = a;
    }

    // ---- epilogue: normalized probs, coalesced float4 writes ----
    for (int lin = tid; lin < QT * (SS / 4); lin += THREADS) {
        int qi = lin / (SS / 4);
        int kc = lin % (SS / 4);
        float rinv = 1.0f / rowsum[qi];
        float4 p = *(const float4*)(Ps + qi * PS + 4 * kc);
        p.x *= rinv; p.y *= rinv; p.z *= rinv; p.w *= rinv;
        *(float4*)(probs + ((size_t)bh * SS + q0 + qi) * SS + 4 * kc) = p;
    }
}

extern "C" void kernel_launch(void* const* d_in, const int* in_sizes, int n_in,
                              void* d_out, int out_size)
{
    const float* q    = (const float*)d_in[0];
    const float* k    = (const float*)d_in[1];
    const float* v    = (const float*)d_in[2];
    const int*   mask = (const int*)d_in[3];

    float* out   = (float*)d_out;                                   // [B,H,S,D]
    float* probs = (float*)d_out + (size_t)BB * HH * SS * DD;       // [B,H,S,S]

    cudaFuncSetAttribute(attn_fused_kernel,
                         cudaFuncAttributeMaxDynamicSharedMemorySize, SMEM_BYTES);

    dim3 grid(SS / QT, BB * HH);   // (128, 24) = 3072 blocks
    attn_fused_kernel<<<grid, THREADS, SMEM_BYTES>>>(q, k, v, mask, out, probs);
}

// round 4
// speedup vs baseline: 2.0513x; 2.0513x over previous
#include <cuda_runtime.h>
#include <cuda_bf16.h>
#include <cstdint>
#include <cstddef>

#define BB 2
#define HH 12
#define SS 2048
#define DD 64
#define MT 128              // q rows per block
#define NK 128              // keys per chunk
#define NCH (SS/NK)         // 16
#define THREADS 256

// ---- smem byte offsets ----
#define SM_MASK 0                     // 128 ints
#define SM_RS   512                   // 128 floats (stores 1/rowsum)
#define SM_KHI  1024                  // 128x64 bf16 (16KB), swizzled; Q hi staged here initially
#define SM_KLO  (SM_KHI + 16384)
#define SM_VHI  (SM_KLO + 16384)
#define SM_VLO  (SM_VHI + 16384)
#define SM_TOTAL (SM_VLO + 16384)     // 66560 B

__device__ __forceinline__ uint32_t smem_u32(const void* p) {
    uint32_t a;
    asm("{ .reg .u64 t; cvta.to.shared.u64 t, %1; cvt.u32.u64 %0, t; }" : "=r"(a) : "l"(p));
    return a;
}

// swizzled byte offset within a 128x(64 bf16) tile: 128B rows, 16B chunks XOR row&7
__device__ __forceinline__ uint32_t swz(int row, int ch) {
    return (uint32_t)(row * 128 + ((ch ^ (row & 7)) << 4));
}

__device__ __forceinline__ void ldmx4(uint32_t* r, uint32_t addr) {
    asm volatile("ldmatrix.sync.aligned.m8n8.x4.shared.b16 {%0,%1,%2,%3}, [%4];"
                 : "=r"(r[0]), "=r"(r[1]), "=r"(r[2]), "=r"(r[3]) : "r"(addr));
}
__device__ __forceinline__ void ldmx4t(uint32_t* r, uint32_t addr) {
    asm volatile("ldmatrix.sync.aligned.m8n8.x4.trans.shared.b16 {%0,%1,%2,%3}, [%4];"
                 : "=r"(r[0]), "=r"(r[1]), "=r"(r[2]), "=r"(r[3]) : "r"(addr));
}
__device__ __forceinline__ void mma16816(float* d, const uint32_t* a, const uint32_t* b) {
    asm volatile("mma.sync.aligned.m16n8k16.row.col.f32.bf16.bf16.f32 "
                 "{%0,%1,%2,%3}, {%4,%5,%6,%7}, {%8,%9}, {%0,%1,%2,%3};"
                 : "+f"(d[0]), "+f"(d[1]), "+f"(d[2]), "+f"(d[3])
                 : "r"(a[0]), "r"(a[1]), "r"(a[2]), "r"(a[3]), "r"(b[0]), "r"(b[1]));
}

// split two fp32 into bf16x2 hi word + bf16x2 residual word (a -> low half)
__device__ __forceinline__ void cvt_split(float a, float b, uint32_t& hw, uint32_t& lw) {
    __nv_bfloat16 ha = __float2bfloat16(a), hb = __float2bfloat16(b);
    float ra = a - __bfloat162float(ha);
    float rb = b - __bfloat162float(hb);
    hw = ((uint32_t)__bfloat16_as_ushort(hb) << 16) | (uint32_t)__bfloat16_as_ushort(ha);
    __nv_bfloat16 la = __float2bfloat16(ra), lb = __float2bfloat16(rb);
    lw = ((uint32_t)__bfloat16_as_ushort(lb) << 16) | (uint32_t)__bfloat16_as_ushort(la);
}

extern __shared__ char smem[];

// stage a [128][64] fp32 tile as bf16 hi/lo into swizzled smem tiles
__device__ __forceinline__ void stage_tile(const float* __restrict__ src,
                                           char* hib, char* lob, float scale, int tid) {
    #pragma unroll
    for (int it = 0; it < 16; ++it) {
        int lin = it * THREADS + tid;
        int r  = lin >> 5;          // row 0..127
        int dp = lin & 31;          // float-pair index 0..31
        float2 t = *(const float2*)(src + r * DD + 2 * dp);
        uint32_t hw, lw;
        cvt_split(t.x * scale, t.y * scale, hw, lw);
        uint32_t off = (uint32_t)(r * 128) + ((((dp >> 2) ^ (r & 7)) << 4)) + ((dp & 3) << 2);
        *(uint32_t*)(hib + off) = hw;
        *(uint32_t*)(lob + off) = lw;
    }
}

__global__ __launch_bounds__(THREADS, 1)
void attn_hmma_kernel(const float* __restrict__ q,
                      const float* __restrict__ k,
                      const float* __restrict__ v,
                      const int*   __restrict__ mask,
                      float* __restrict__ out,
                      float* __restrict__ probs)
{
    const uint32_t sbase = smem_u32(smem);
    const int tid = threadIdx.x;
    const int wid = tid >> 5;       // warp 0..7 -> q rows 16w..16w+15
    const int lid = tid & 31;
    const int grp = lid >> 3;       // ldmatrix address group
    const int lr  = lid & 7;
    const int q4  = lid & 3;        // col-pair selector in fragments
    const int r4  = lid >> 2;       // row-in-8 selector

    const int bh = blockIdx.y;
    const int b  = bh / HH;
    const int q0 = blockIdx.x * MT;
    const size_t bhrow = (size_t)bh * SS + q0;

    const float* qptr  = q + bhrow * DD;
    const float* kbase = k + (size_t)bh * SS * DD;
    const float* vbase = v + (size_t)bh * SS * DD;
    const int*   mbase = mask + b * SS;
    const int*   Msp   = (const int*)(smem + SM_MASK);

    // ---- stage Q (prescaled by 1/8) into K buffers, load A-fragments, keep in regs ----
    stage_tile(qptr, smem + SM_KHI, smem + SM_KLO, 0.125f, tid);
    __syncthreads();

    uint32_t qh[4][4], ql[4][4];
    #pragma unroll
    for (int c = 0; c < 4; ++c) {
        int row = 16 * wid + ((grp & 1) << 3) + lr;
        int ch  = 2 * c + (grp >> 1);
        ldmx4(qh[c], sbase + SM_KHI + swz(row, ch));
        ldmx4(ql[c], sbase + SM_KLO + swz(row, ch));
    }

    float oacc[8][4];
    #pragma unroll
    for (int n = 0; n < 8; ++n)
        #pragma unroll
        for (int i = 0; i < 4; ++i) oacc[n][i] = 0.0f;
    float rsum0 = 0.0f, rsum1 = 0.0f;

    for (int c = 0; c < NCH; ++c) {
        __syncthreads();   // previous chunk's smem reads done (also Q frag loads at c=0)
        stage_tile(kbase + (size_t)c * NK * DD, smem + SM_KHI, smem + SM_KLO, 1.0f, tid);
        stage_tile(vbase + (size_t)c * NK * DD, smem + SM_VHI, smem + SM_VLO, 1.0f, tid);
        if (tid < NK) ((int*)(smem + SM_MASK))[tid] = mbase[c * NK + tid];
        __syncthreads();

        // ---- QK^T: S[16 x 128] per warp, hi/lo split (3 products) ----
        float sc[16][4];
        #pragma unroll
        for (int t = 0; t < 16; ++t)
            #pragma unroll
            for (int i = 0; i < 4; ++i) sc[t][i] = 0.0f;

        #pragma unroll
        for (int np = 0; np < 8; ++np) {        // key n-tile pair (16 keys)
            int krow = 16 * np + ((grp >> 1) << 3) + lr;
            #pragma unroll
            for (int cc = 0; cc < 4; ++cc) {    // k-step over d
                int ch = 2 * cc + (grp & 1);
                uint32_t bhv[4], blv[4];
                ldmx4(bhv, sbase + SM_KHI + swz(krow, ch));
                ldmx4(blv, sbase + SM_KLO + swz(krow, ch));
                mma16816(sc[2*np],   qh[cc], bhv + 0);
                mma16816(sc[2*np],   qh[cc], blv + 0);
                mma16816(sc[2*np],   ql[cc], bhv + 0);
                mma16816(sc[2*np+1], qh[cc], bhv + 2);
                mma16816(sc[2*np+1], qh[cc], blv + 2);
                mma16816(sc[2*np+1], ql[cc], bhv + 2);
            }
        }

        // ---- epilogue: mask + exp, probs store, rowsum, pack P as A-fragments ----
        float* prow = probs + (bhrow + 16 * wid + r4) * SS + c * NK;
        #pragma unroll
        for (int t = 0; t < 16; ++t) {
            int col = 8 * t + 2 * q4;
            float m0 = Msp[col]     ? 1.0f : 0.0f;
            float m1 = Msp[col + 1] ? 1.0f : 0.0f;
            float p0 = m0 * __expf(sc[t][0]);
            float p1 = m1 * __expf(sc[t][1]);
            float p2 = m0 * __expf(sc[t][2]);
            float p3 = m1 * __expf(sc[t][3]);
            rsum0 += p0 + p1; rsum1 += p2 + p3;
            *(float2*)(prow + col)          = make_float2(p0, p1);
            *(float2*)(prow + 8 * SS + col) = make_float2(p2, p3);
            sc[t][0] = p0; sc[t][1] = p1; sc[t][2] = p2; sc[t][3] = p3;
        }
        uint32_t ahi[8][4], alo[8][4];
        #pragma unroll
        for (int j = 0; j < 8; ++j) {
            cvt_split(sc[2*j][0],   sc[2*j][1],   ahi[j][0], alo[j][0]);
            cvt_split(sc[2*j][2],   sc[2*j][3],   ahi[j][1], alo[j][1]);
            cvt_split(sc[2*j+1][0], sc[2*j+1][1], ahi[j][2], alo[j][2]);
            cvt_split(sc[2*j+1][2], sc[2*j+1][3], ahi[j][3], alo[j][3]);
        }

        // ---- PV: out[16 x 64] += P · V, hi/lo split ----
        #pragma unroll
        for (int np = 0; np < 4; ++np) {        // d n-tile pair (16 d)
            #pragma unroll
            for (int j = 0; j < 8; ++j) {       // k-step over keys
                int vrow = 16 * j + ((grp & 1) << 3) + lr;
                int ch   = 2 * np + (grp >> 1);
                uint32_t vh[4], vl[4];
                ldmx4t(vh, sbase + SM_VHI + swz(vrow, ch));
                ldmx4t(vl, sbase + SM_VLO + swz(vrow, ch));
                mma16816(oacc[2*np],   ahi[j], vh + 0);
                mma16816(oacc[2*np],   ahi[j], vl + 0);
                mma16816(oacc[2*np],   alo[j], vh + 0);
                mma16816(oacc[2*np+1], ahi[j], vh + 2);
                mma16816(oacc[2*np+1], ahi[j], vl + 2);
                mma16816(oacc[2*np+1], alo[j], vh + 2);
            }
        }
    }

    // ---- rowsum reduce (quad), write out normalized ----
    rsum0 += __shfl_xor_sync(0xFFFFFFFFu, rsum0, 1);
    rsum0 += __shfl_xor_sync(0xFFFFFFFFu, rsum0, 2);
    rsum1 += __shfl_xor_sync(0xFFFFFFFFu, rsum1, 1);
    rsum1 += __shfl_xor_sync(0xFFFFFFFFu, rsum1, 2);
    float rinv0 = 1.0f / rsum0, rinv1 = 1.0f / rsum1;
    float* rs = (float*)(smem + SM_RS);
    if (q4 == 0) { rs[16 * wid + r4] = rinv0; rs[16 * wid + r4 + 8] = rinv1; }

    float* orow = out + (bhrow + 16 * wid + r4) * DD;
    #pragma unroll
    for (int n = 0; n < 8; ++n) {
        int col = 8 * n + 2 * q4;
        *(float2*)(orow + col)          = make_float2(oacc[n][0] * rinv0, oacc[n][1] * rinv0);
        *(float2*)(orow + 8 * DD + col) = make_float2(oacc[n][2] * rinv1, oacc[n][3] * rinv1);
    }

    __syncthreads();

    // ---- normalize probs (RMW; block's own 1MB slice, mostly L2-hot) ----
    {
        int rown = tid >> 1, half = tid & 1;
        float ri = rs[rown];
        float* pr = probs + (bhrow + rown) * SS + half * (SS / 2);
        #pragma unroll 4
        for (int i = 0; i < (SS / 2) / 4; ++i) {
            float4 t = *(float4*)(pr + 4 * i);
            t.x *= ri; t.y *= ri; t.z *= ri; t.w *= ri;
            *(float4*)(pr + 4 * i) = t;
        }
    }
}

extern "C" void kernel_launch(void* const* d_in, const int* in_sizes, int n_in,
                              void* d_out, int out_size)
{
    const float* q    = (const float*)d_in[0];
    const float* k    = (const float*)d_in[1];
    const float* v    = (const float*)d_in[2];
    const int*   mask = (const int*)d_in[3];

    float* out   = (float*)d_out;
    float* probs = (float*)d_out + (size_t)BB * HH * SS * DD;

    cudaFuncSetAttribute(attn_hmma_kernel,
                         cudaFuncAttributeMaxDynamicSharedMemorySize, SM_TOTAL);

    dim3 grid(SS / MT, BB * HH);   // (16, 24) = 384 blocks
    attn_hmma_kernel<<<grid, THREADS, SM_TOTAL>>>(q, k, v, mask, out, probs);
}